// round 5
// baseline (speedup 1.0000x reference)
#include <cuda_runtime.h>
#include <string.h>

// ---------------------------------------------------------------------------
// Photonic FFN: 6-mode cutoff-2 Fock circuit per row, probs=|amp|^2, +x, LN.
// One thread = one sample. State: 64 complex amps packed as float2 pairs
// along the wire-5 bit (amp index a = 2p + lane). Gates on wires 0..4 are
// purely elementwise on packed regs -> fma.rn.f32x2 (2x FMA-pipe density).
// Global I/O staged through shared memory for full coalescing.
// ---------------------------------------------------------------------------

typedef unsigned long long u64;

static __device__ __forceinline__ float2 f2(float a, float b) { return make_float2(a, b); }
static __device__ __forceinline__ float2 bc(float a) { return make_float2(a, a); }

static __device__ __forceinline__ float2 fma2(float2 a, float2 b, float2 c) {
    u64 ua, ub, uc, ud;
    memcpy(&ua, &a, 8); memcpy(&ub, &b, 8); memcpy(&uc, &c, 8);
    asm("fma.rn.f32x2 %0, %1, %2, %3;" : "=l"(ud) : "l"(ua), "l"(ub), "l"(uc));
    float2 d; memcpy(&d, &ud, 8); return d;
}
static __device__ __forceinline__ float2 mul2(float2 a, float2 b) {
    u64 ua, ub, ud;
    memcpy(&ua, &a, 8); memcpy(&ub, &b, 8);
    asm("mul.rn.f32x2 %0, %1, %2;" : "=l"(ud) : "l"(ua), "l"(ub));
    float2 d; memcpy(&d, &ud, 8); return d;
}
static __device__ __forceinline__ float2 add2(float2 a, float2 b) {
    u64 ua, ub, ud;
    memcpy(&ua, &a, 8); memcpy(&ub, &b, 8);
    asm("add.rn.f32x2 %0, %1, %2;" : "=l"(ud) : "l"(ua), "l"(ub));
    float2 d; memcpy(&d, &ud, 8); return d;
}

// ---- packed gates (p-space: 32 float2 reals R, 32 float2 imags I) ----------

// rotation on wire bit PBIT (amp bit = 2*PBIT): amps with bit set *= (cr + i ci)
template <int PBIT>
static __device__ __forceinline__ void rot_p(float2* R, float2* I, float cr, float ci) {
    const float2 vcr = bc(cr), vci = bc(ci), vnci = bc(-ci);
#pragma unroll
    for (int p = 0; p < 32; ++p) {
        if (p & PBIT) {
            float2 r = R[p], i = I[p];
            R[p] = fma2(i, vnci, mul2(r, vcr));
            I[p] = fma2(i, vcr, mul2(r, vci));
        }
    }
}

// rotation on wire 5 (amp bit 1 = lane): scalar on .y components
static __device__ __forceinline__ void rot_l(float2* R, float2* I, float cr, float ci) {
#pragma unroll
    for (int p = 0; p < 32; ++p) {
        float r = R[p].y, i = I[p].y;
        R[p].y = r * cr - i * ci;
        I[p].y = r * ci + i * cr;
    }
}

// diag (fused rot+squeeze): clear amps *= d0 (real), set amps *= (c1r + i c1i)
template <int PBIT>
static __device__ __forceinline__ void diag_p(float2* R, float2* I,
                                              float d0, float c1r, float c1i) {
    const float2 vd0 = bc(d0), vcr = bc(c1r), vci = bc(c1i), vnci = bc(-c1i);
#pragma unroll
    for (int p = 0; p < 32; ++p) {
        float2 r = R[p], i = I[p];
        if (p & PBIT) {
            R[p] = fma2(i, vnci, mul2(r, vcr));
            I[p] = fma2(i, vcr, mul2(r, vci));
        } else {
            R[p] = mul2(r, vd0);
            I[p] = mul2(i, vd0);
        }
    }
}

// diag on wire 5: mixed constant vector, fully elementwise
static __device__ __forceinline__ void diag_l(float2* R, float2* I,
                                              float d0, float c1r, float c1i) {
    const float2 va = f2(d0, c1r), vb = f2(0.0f, c1i), vnb = f2(0.0f, -c1i);
#pragma unroll
    for (int p = 0; p < 32; ++p) {
        float2 r = R[p], i = I[p];
        R[p] = fma2(i, vnb, mul2(r, va));
        I[p] = fma2(i, va, mul2(r, vb));
    }
}

// real 2x2 displacement on wire bit PBIT (amp bit = 2*PBIT)
template <int PBIT>
static __device__ __forceinline__ void disp_p(float2* R, float2* I,
                                              float m00, float m01, float m10, float m11) {
    const float2 v00 = bc(m00), v01 = bc(m01), v10 = bc(m10), v11 = bc(m11);
#pragma unroll
    for (int p = 0; p < 32; ++p) {
        if (!(p & PBIT)) {
            const int q = p | PBIT;
            float2 r0 = R[p], r1 = R[q], i0 = I[p], i1 = I[q];
            R[p] = fma2(r1, v01, mul2(r0, v00));
            R[q] = fma2(r1, v11, mul2(r0, v10));
            I[p] = fma2(i1, v01, mul2(i0, v00));
            I[q] = fma2(i1, v11, mul2(i0, v10));
        }
    }
}

// real 2x2 displacement on wire 5: within-pair (scalar components)
static __device__ __forceinline__ void disp_l(float2* R, float2* I,
                                              float m00, float m01, float m10, float m11) {
#pragma unroll
    for (int p = 0; p < 32; ++p) {
        float re = R[p].x, ro = R[p].y, ie = I[p].x, io = I[p].y;
        R[p].x = m00 * re + m01 * ro;
        R[p].y = m10 * re + m11 * ro;
        I[p].x = m00 * ie + m01 * io;
        I[p].y = m10 * ie + m11 * io;
    }
}

// beamsplitter, both wire bits >= wire4 (amp bits >= 2): pure packed
template <int PA, int PB>
static __device__ __forceinline__ void bs_p(float2* R, float2* I,
                                            float c, float br, float bi, float c2) {
    const float2 vc = bc(c), vbr = bc(br), vbi = bc(bi);
    const float2 vnbr = bc(-br), vnbi = bc(-bi), vc2 = bc(c2);
#pragma unroll
    for (int p = 0; p < 32; ++p) {
        if ((p & (PA | PB)) == 0) {
            const int p01 = p | PB, p10 = p | PA, p11 = p | PA | PB;
            float2 xr = R[p01], xi = I[p01], yr = R[p10], yi = I[p10];
            R[p01] = fma2(yi, vnbi, fma2(yr, vbr, mul2(xr, vc)));
            I[p01] = fma2(yr, vbi, fma2(yi, vbr, mul2(xi, vc)));
            R[p10] = fma2(xi, vnbi, fma2(xr, vnbr, mul2(yr, vc)));
            I[p10] = fma2(xr, vbi, fma2(xi, vnbr, mul2(yi, vc)));
            R[p11] = mul2(R[p11], vc2);
            I[p11] = mul2(I[p11], vc2);
        }
    }
}

// beamsplitter on wires (4,5) = amp bits (2,1): lane-mixing, scalar components
static __device__ __forceinline__ void bs_m(float2* R, float2* I,
                                            float c, float br, float bi, float c2) {
#pragma unroll
    for (int p = 0; p < 32; p += 2) {
        float xr = R[p].y, xi = I[p].y, yr = R[p + 1].x, yi = I[p + 1].x;
        R[p].y = c * xr + br * yr - bi * yi;
        I[p].y = c * xi + br * yi + bi * yr;
        R[p + 1].x = c * yr - br * xr - bi * xi;
        I[p + 1].x = c * yi - br * xi + bi * xr;
        R[p + 1].y *= c2;
        I[p + 1].y *= c2;
    }
}

#define V(k) __ldg(v + (k))

#define BS_COEF(TH, PH, BODY)                                          \
    do {                                                               \
        float s_, c_, sp_, cp_;                                        \
        __sincosf((TH), &s_, &c_);                                     \
        __sincosf((PH), &sp_, &cp_);                                   \
        float br_ = s_ * cp_, bi_ = s_ * sp_, c2_ = c_ * c_ - s_ * s_; \
        BODY;                                                          \
    } while (0)

#define BS_P(PA, PB, TH, PH) BS_COEF(TH, PH, (bs_p<PA, PB>(Rr, Ri, c_, br_, bi_, c2_)))
#define BS_M(TH, PH) BS_COEF(TH, PH, (bs_m(Rr, Ri, c_, br_, bi_, c2_)))

#define DIAG_COEF(PH, RR, BODY)                                        \
    do {                                                               \
        float r_ = (RR);                                               \
        float e_ = __expf(r_);                                         \
        float ch_ = 0.5f * (e_ + __fdividef(1.0f, e_));                \
        float d0_ = rsqrtf(ch_);                                       \
        float d1_ = d0_ * __fdividef(1.0f, ch_);                       \
        float sn_, cs_;                                                \
        __sincosf((PH), &sn_, &cs_);                                   \
        float c1r_ = d1_ * cs_, c1i_ = d1_ * sn_;                      \
        BODY;                                                          \
    } while (0)

#define DIAG_P(PBIT, PH, RR) DIAG_COEF(PH, RR, (diag_p<PBIT>(Rr, Ri, d0_, c1r_, c1i_)))
#define DIAG_L(PH, RR) DIAG_COEF(PH, RR, (diag_l(Rr, Ri, d0_, c1r_, c1i_)))

#define DISP_COEF(RD, BODY)                                            \
    do {                                                               \
        float r_ = (RD);                                               \
        float p_ = __expf(-0.5f * r_ * r_);                            \
        float m00_ = p_, m01_ = -p_ * r_, m10_ = p_ * r_;              \
        float m11_ = p_ * (1.0f - r_ * r_);                            \
        BODY;                                                          \
    } while (0)

#define ROTDISP_P(PBIT, PH, RD)                                        \
    do {                                                               \
        float sn_, cs_;                                                \
        __sincosf((PH), &sn_, &cs_);                                   \
        rot_p<PBIT>(Rr, Ri, cs_, sn_);                                 \
        DISP_COEF(RD, (disp_p<PBIT>(Rr, Ri, m00_, m01_, m10_, m11_))); \
    } while (0)

#define ROTDISP_L(PH, RD)                                              \
    do {                                                               \
        float sn_, cs_;                                                \
        __sincosf((PH), &sn_, &cs_);                                   \
        rot_l(Rr, Ri, cs_, sn_);                                       \
        DISP_COEF(RD, (disp_l(Rr, Ri, m00_, m01_, m10_, m11_)));       \
    } while (0)

#define ROT_P(PBIT, PH)                                                \
    do {                                                               \
        float sn_, cs_;                                                \
        __sincosf((PH), &sn_, &cs_);                                   \
        rot_p<PBIT>(Rr, Ri, cs_, sn_);                                 \
    } while (0)

#define ROT_L(PH)                                                      \
    do {                                                               \
        float sn_, cs_;                                                \
        __sincosf((PH), &sn_, &cs_);                                   \
        rot_l(Rr, Ri, cs_, sn_);                                       \
    } while (0)

static const int SROW = 66;  // smem row stride (floats): even (float2-aligned), low conflict

__global__ void __launch_bounds__(128)
ffb_kernel(const float* __restrict__ x, const float* __restrict__ var,
           const float* __restrict__ gamma, const float* __restrict__ beta,
           float* __restrict__ out) {
    __shared__ float sm[128 * SROW];

    const int t = threadIdx.x;
    const long long r0 = (long long)blockIdx.x * 128;

    // ---- stage x rows into smem (fully coalesced float4 loads) ----
    {
        const float4* gx = (const float4*)(x + r0 * 64);
#pragma unroll
        for (int k = 0; k < 16; ++k) {
            int g = t + 128 * k;           // float4 index within block tile
            int row = g >> 4, c4 = g & 15;
            float4 v = gx[g];
            float* d = sm + row * SROW + c4 * 4;
            *(float2*)d = f2(v.x, v.y);
            *(float2*)(d + 2) = f2(v.z, v.w);
        }
    }
    __syncthreads();

    const float* xs = sm + t * SROW;  // this thread's row

    float2 Rr[32], Ri[32];

    // ---------------- Encoding collapses to a product state -----------------
    {
        float Ar[6], Brr[6], Bri[6];
#pragma unroll
        for (int w = 0; w < 6; ++w) {
            float r1 = xs[2 * w];
            float e1 = __expf(r1);
            float ch1 = 0.5f * (e1 + __fdividef(1.0f, e1));
            float cw = rsqrtf(ch1);  // sqrt(sech r1)

            float rd = xs[28 + 2 * w];
            float phid = xs[29 + 2 * w];
            float pref = __expf(-0.5f * rd * rd);

            float kk = xs[40 + w];

            float r2 = xs[46 + 2 * w];
            float e2 = __expf(r2);
            float ch2 = 0.5f * (e2 + __fdividef(1.0f, e2));
            float s0 = rsqrtf(ch2);                 // sech^0.5
            float s1 = s0 * __fdividef(1.0f, ch2);  // sech^1.5

            float phr = xs[58 + w];
            float ang = phid + kk + phr;
            float sn, cs;
            __sincosf(ang, &sn, &cs);

            float base = cw * pref;
            Ar[w] = base * s0;
            float bm = base * rd * s1;
            Brr[w] = bm * cs;
            Bri[w] = bm * sn;
        }
        // packed outer product; lane = wire5 bit
        Rr[0] = f2(Ar[5], Brr[5]);
        Ri[0] = f2(0.0f, Bri[5]);
#pragma unroll
        for (int w = 4; w >= 0; --w) {
            const int PL = 1 << (4 - w);
            const float2 vA = bc(Ar[w]), vBr = bc(Brr[w]), vBi = bc(Bri[w]), vnBi = bc(-Bri[w]);
#pragma unroll
            for (int j = 0; j < 16; ++j) {
                if (j < PL) {
                    float2 ar = Rr[j], ai = Ri[j];
                    Rr[PL + j] = fma2(ai, vnBi, mul2(ar, vBr));
                    Ri[PL + j] = fma2(ai, vBr, mul2(ar, vBi));
                    Rr[j] = mul2(ar, vA);
                    Ri[j] = mul2(ai, vA);
                }
            }
        }
    }

    // ---------------- Variational layers ------------------------------------
#pragma unroll 1
    for (int l = 0; l < 2; ++l) {
        const float* v = var + l * 50;

        // BS chain 1: wires (0,1)..(4,5) = amp bits (32,16)..(2,1) = p bits /2
        BS_P(16, 8, V(0), V(1));
        BS_P(8, 4, V(2), V(3));
        BS_P(4, 2, V(4), V(5));
        BS_P(2, 1, V(6), V(7));
        BS_M(V(8), V(9));

        // rot (v[10:16]) fused with squeeze (v[16:22])
        DIAG_P(16, V(10), V(16));
        DIAG_P(8, V(11), V(17));
        DIAG_P(4, V(12), V(18));
        DIAG_P(2, V(13), V(19));
        DIAG_P(1, V(14), V(20));
        DIAG_L(V(15), V(21));

        // BS chain 2 (v[22:32])
        BS_P(16, 8, V(22), V(23));
        BS_P(8, 4, V(24), V(25));
        BS_P(4, 2, V(26), V(27));
        BS_P(2, 1, V(28), V(29));
        BS_M(V(30), V(31));

        // rot (v[32:38]) + real displacement (v[38:44], phi = 0)
        ROTDISP_P(16, V(32), V(38));
        ROTDISP_P(8, V(33), V(39));
        ROTDISP_P(4, V(34), V(40));
        ROTDISP_P(2, V(35), V(41));
        ROTDISP_P(1, V(36), V(42));
        ROTDISP_L(V(37), V(43));

        // Kerr rotations (v[44:50]) — pure phases: skip on last layer
        if (l == 0) {
            ROT_P(16, V(44));
            ROT_P(8, V(45));
            ROT_P(4, V(46));
            ROT_P(2, V(47));
            ROT_P(1, V(48));
            ROT_L(V(49));
        }
    }

    // ---------------- probs + residual + LayerNorm ---------------------------
    float2 acc = f2(0.0f, 0.0f);
#pragma unroll
    for (int p = 0; p < 32; ++p) {
        float2 pr = fma2(Rr[p], Rr[p], mul2(Ri[p], Ri[p]));
        float2 xv = *(const float2*)(xs + 2 * p);
        float2 y = add2(pr, xv);
        Rr[p] = y;  // reuse as y storage
        acc = add2(acc, y);
    }
    float mean = (acc.x + acc.y) * 0.015625f;
    float2 vacc = f2(0.0f, 0.0f);
    const float2 vnm = bc(-mean);
#pragma unroll
    for (int p = 0; p < 32; ++p) {
        float2 d = add2(Rr[p], vnm);
        Rr[p] = d;
        vacc = fma2(d, d, vacc);
    }
    float inv = rsqrtf((vacc.x + vacc.y) * 0.015625f + 1e-5f);
    const float2 vinv = bc(inv);

    float* ys = sm + t * SROW;
    const float2* g2 = (const float2*)gamma;
    const float2* b2 = (const float2*)beta;
#pragma unroll
    for (int p = 0; p < 32; ++p) {
        float2 o = fma2(mul2(Rr[p], vinv), __ldg(g2 + p), __ldg(b2 + p));
        *(float2*)(ys + 2 * p) = o;
    }
    __syncthreads();

    // ---- coalesced float4 stores ----
    {
        float4* go = (float4*)(out + r0 * 64);
#pragma unroll
        for (int k = 0; k < 16; ++k) {
            int g = t + 128 * k;
            int row = g >> 4, c4 = g & 15;
            const float* s = sm + row * SROW + c4 * 4;
            float2 a = *(const float2*)s;
            float2 b = *(const float2*)(s + 2);
            go[g] = make_float4(a.x, a.y, b.x, b.y);
        }
    }
}

extern "C" void kernel_launch(void* const* d_in, const int* in_sizes, int n_in,
                              void* d_out, int out_size) {
    const float* x = (const float*)d_in[0];
    const float* var = (const float*)d_in[1];
    const float* gamma = (const float*)d_in[2];
    const float* beta = (const float*)d_in[3];
    float* out = (float*)d_out;

    int nrows = in_sizes[0] / 64;  // 131072, divisible by 128
    int blocks = nrows / 128;
    ffb_kernel<<<blocks, 128>>>(x, var, gamma, beta, out);
}

// round 10
// speedup vs baseline: 1.0541x; 1.0541x over previous
#include <cuda_runtime.h>
#include <cstdint>
#include <string.h>

typedef unsigned long long u64;

static __device__ __forceinline__ float2 f2(float a, float b) { return make_float2(a, b); }
static __device__ __forceinline__ float2 bc(float a) { return make_float2(a, a); }

static __device__ __forceinline__ float2 fma2(float2 a, float2 b, float2 c) {
    u64 ua, ub, uc, ud;
    memcpy(&ua, &a, 8); memcpy(&ub, &b, 8); memcpy(&uc, &c, 8);
    asm("fma.rn.f32x2 %0, %1, %2, %3;" : "=l"(ud) : "l"(ua), "l"(ub), "l"(uc));
    float2 d; memcpy(&d, &ud, 8); return d;
}
static __device__ __forceinline__ float2 mul2(float2 a, float2 b) {
    u64 ua, ub, ud;
    memcpy(&ua, &a, 8); memcpy(&ub, &b, 8);
    asm("mul.rn.f32x2 %0, %1, %2;" : "=l"(ud) : "l"(ua), "l"(ub));
    float2 d; memcpy(&d, &ud, 8); return d;
}
static __device__ __forceinline__ float tf32r(float v) {
    unsigned u; asm("cvt.rna.tf32.f32 %0, %1;" : "=r"(u) : "f"(v));
    return __uint_as_float(u);
}

// ---------------- packed gate set (for U build only) -------------------------
template <int PBIT>
static __device__ __forceinline__ void rot_p(float2* R, float2* I, float cr, float ci) {
    const float2 vcr = bc(cr), vci = bc(ci), vnci = bc(-ci);
#pragma unroll
    for (int p = 0; p < 32; ++p)
        if (p & PBIT) {
            float2 r = R[p], i = I[p];
            R[p] = fma2(i, vnci, mul2(r, vcr));
            I[p] = fma2(i, vcr, mul2(r, vci));
        }
}
static __device__ __forceinline__ void rot_l(float2* R, float2* I, float cr, float ci) {
#pragma unroll
    for (int p = 0; p < 32; ++p) {
        float r = R[p].y, i = I[p].y;
        R[p].y = r * cr - i * ci;
        I[p].y = r * ci + i * cr;
    }
}
template <int PBIT>
static __device__ __forceinline__ void diag_p(float2* R, float2* I, float d0, float c1r, float c1i) {
    const float2 vd0 = bc(d0), vcr = bc(c1r), vci = bc(c1i), vnci = bc(-c1i);
#pragma unroll
    for (int p = 0; p < 32; ++p) {
        float2 r = R[p], i = I[p];
        if (p & PBIT) {
            R[p] = fma2(i, vnci, mul2(r, vcr));
            I[p] = fma2(i, vcr, mul2(r, vci));
        } else {
            R[p] = mul2(r, vd0);
            I[p] = mul2(i, vd0);
        }
    }
}
static __device__ __forceinline__ void diag_l(float2* R, float2* I, float d0, float c1r, float c1i) {
    const float2 va = f2(d0, c1r), vb = f2(0.0f, c1i), vnb = f2(0.0f, -c1i);
#pragma unroll
    for (int p = 0; p < 32; ++p) {
        float2 r = R[p], i = I[p];
        R[p] = fma2(i, vnb, mul2(r, va));
        I[p] = fma2(i, va, mul2(r, vb));
    }
}
template <int PBIT>
static __device__ __forceinline__ void disp_p(float2* R, float2* I, float m00, float m01, float m10, float m11) {
    const float2 v00 = bc(m00), v01 = bc(m01), v10 = bc(m10), v11 = bc(m11);
#pragma unroll
    for (int p = 0; p < 32; ++p)
        if (!(p & PBIT)) {
            const int q = p | PBIT;
            float2 r0 = R[p], r1 = R[q], i0 = I[p], i1 = I[q];
            R[p] = fma2(r1, v01, mul2(r0, v00));
            R[q] = fma2(r1, v11, mul2(r0, v10));
            I[p] = fma2(i1, v01, mul2(i0, v00));
            I[q] = fma2(i1, v11, mul2(i0, v10));
        }
}
static __device__ __forceinline__ void disp_l(float2* R, float2* I, float m00, float m01, float m10, float m11) {
#pragma unroll
    for (int p = 0; p < 32; ++p) {
        float re = R[p].x, ro = R[p].y, ie = I[p].x, io = I[p].y;
        R[p].x = m00 * re + m01 * ro;
        R[p].y = m10 * re + m11 * ro;
        I[p].x = m00 * ie + m01 * io;
        I[p].y = m10 * ie + m11 * io;
    }
}
template <int PA, int PB>
static __device__ __forceinline__ void bs_p(float2* R, float2* I, float c, float br, float bi, float c2) {
    const float2 vc = bc(c), vbr = bc(br), vbi = bc(bi);
    const float2 vnbr = bc(-br), vnbi = bc(-bi), vc2 = bc(c2);
#pragma unroll
    for (int p = 0; p < 32; ++p)
        if ((p & (PA | PB)) == 0) {
            const int p01 = p | PB, p10 = p | PA, p11 = p | PA | PB;
            float2 xr = R[p01], xi = I[p01], yr = R[p10], yi = I[p10];
            R[p01] = fma2(yi, vnbi, fma2(yr, vbr, mul2(xr, vc)));
            I[p01] = fma2(yr, vbi, fma2(yi, vbr, mul2(xi, vc)));
            R[p10] = fma2(xi, vnbi, fma2(xr, vnbr, mul2(yr, vc)));
            I[p10] = fma2(xr, vbi, fma2(xi, vnbr, mul2(yi, vc)));
            R[p11] = mul2(R[p11], vc2);
            I[p11] = mul2(I[p11], vc2);
        }
}
static __device__ __forceinline__ void bs_m(float2* R, float2* I, float c, float br, float bi, float c2) {
#pragma unroll
    for (int p = 0; p < 32; p += 2) {
        float xr = R[p].y, xi = I[p].y, yr = R[p + 1].x, yi = I[p + 1].x;
        R[p].y = c * xr + br * yr - bi * yi;
        I[p].y = c * xi + br * yi + bi * yr;
        R[p + 1].x = c * yr - br * xr - bi * xi;
        I[p + 1].x = c * yi - br * xi + bi * xr;
        R[p + 1].y *= c2;
        I[p + 1].y *= c2;
    }
}

#define V(k) __ldg(v + (k))
#define BS_COEF(TH, PH, BODY) do { \
    float s_, c_, sp_, cp_; __sincosf((TH), &s_, &c_); __sincosf((PH), &sp_, &cp_); \
    float br_ = s_ * cp_, bi_ = s_ * sp_, c2_ = c_ * c_ - s_ * s_; BODY; } while (0)
#define BS_P(PA, PB, TH, PH) BS_COEF(TH, PH, (bs_p<PA, PB>(Rr, Ri, c_, br_, bi_, c2_)))
#define BS_M(TH, PH) BS_COEF(TH, PH, (bs_m(Rr, Ri, c_, br_, bi_, c2_)))
#define DIAG_COEF(PH, RR, BODY) do { \
    float r_ = (RR); float e_ = __expf(r_); float ch_ = 0.5f * (e_ + __fdividef(1.0f, e_)); \
    float d0_ = rsqrtf(ch_); float d1_ = d0_ * __fdividef(1.0f, ch_); \
    float sn_, cs_; __sincosf((PH), &sn_, &cs_); \
    float c1r_ = d1_ * cs_, c1i_ = d1_ * sn_; BODY; } while (0)
#define DIAG_P(PBIT, PH, RR) DIAG_COEF(PH, RR, (diag_p<PBIT>(Rr, Ri, d0_, c1r_, c1i_)))
#define DIAG_L(PH, RR) DIAG_COEF(PH, RR, (diag_l(Rr, Ri, d0_, c1r_, c1i_)))
#define DISP_COEF(RD, BODY) do { \
    float r_ = (RD); float p_ = __expf(-0.5f * r_ * r_); \
    float m00_ = p_, m01_ = -p_ * r_, m10_ = p_ * r_, m11_ = p_ * (1.0f - r_ * r_); BODY; } while (0)
#define ROTDISP_P(PBIT, PH, RD) do { \
    float sn_, cs_; __sincosf((PH), &sn_, &cs_); rot_p<PBIT>(Rr, Ri, cs_, sn_); \
    DISP_COEF(RD, (disp_p<PBIT>(Rr, Ri, m00_, m01_, m10_, m11_))); } while (0)
#define ROTDISP_L(PH, RD) do { \
    float sn_, cs_; __sincosf((PH), &sn_, &cs_); rot_l(Rr, Ri, cs_, sn_); \
    DISP_COEF(RD, (disp_l(Rr, Ri, m00_, m01_, m10_, m11_))); } while (0)
#define ROT_P(PBIT, PH) do { float sn_, cs_; __sincosf((PH), &sn_, &cs_); rot_p<PBIT>(Rr, Ri, cs_, sn_); } while (0)
#define ROT_L(PH) do { float sn_, cs_; __sincosf((PH), &sn_, &cs_); rot_l(Rr, Ri, cs_, sn_); } while (0)

// ---------------------------------------------------------------------------
// Kernel 1: build realified U (128 rows n = out re/im, 128 cols k = in re/im,
// K-major), tf32-rounded, into device scratch. 64 threads, 1 block.
// ---------------------------------------------------------------------------
__device__ __align__(16) float g_U[16384];

__global__ void __launch_bounds__(64) build_u_kernel(const float* __restrict__ var) {
    const int k0 = threadIdx.x;  // input basis amp 0..63
    float2 Rr[32], Ri[32];
#pragma unroll
    for (int p = 0; p < 32; ++p) { Rr[p] = f2(0.f, 0.f); Ri[p] = f2(0.f, 0.f); }
    if (k0 & 1) Rr[k0 >> 1].y = 1.0f; else Rr[k0 >> 1].x = 1.0f;

#pragma unroll 1
    for (int l = 0; l < 2; ++l) {
        const float* v = var + l * 50;
        BS_P(16, 8, V(0), V(1));  BS_P(8, 4, V(2), V(3));  BS_P(4, 2, V(4), V(5));
        BS_P(2, 1, V(6), V(7));   BS_M(V(8), V(9));
        DIAG_P(16, V(10), V(16)); DIAG_P(8, V(11), V(17)); DIAG_P(4, V(12), V(18));
        DIAG_P(2, V(13), V(19));  DIAG_P(1, V(14), V(20)); DIAG_L(V(15), V(21));
        BS_P(16, 8, V(22), V(23)); BS_P(8, 4, V(24), V(25)); BS_P(4, 2, V(26), V(27));
        BS_P(2, 1, V(28), V(29));  BS_M(V(30), V(31));
        ROTDISP_P(16, V(32), V(38)); ROTDISP_P(8, V(33), V(39)); ROTDISP_P(4, V(34), V(40));
        ROTDISP_P(2, V(35), V(41));  ROTDISP_P(1, V(36), V(42)); ROTDISP_L(V(37), V(43));
        if (l == 0) {  // last-layer Kerr = pure output phases, |amp|^2-invariant
            ROT_P(16, V(44)); ROT_P(8, V(45)); ROT_P(4, V(46));
            ROT_P(2, V(47));  ROT_P(1, V(48)); ROT_L(V(49));
        }
    }

#pragma unroll
    for (int p = 0; p < 32; ++p) {
#pragma unroll
        for (int c = 0; c < 2; ++c) {
            int j = 2 * p + c;  // output amp
            float re = c ? Rr[p].y : Rr[p].x;
            float im = c ? Ri[p].y : Ri[p].x;
            float tre = tf32r(re), tim = tf32r(im);
            g_U[(2 * j) * 128 + 2 * k0]         = tre;
            g_U[(2 * j) * 128 + 2 * k0 + 1]     = tf32r(-im);
            g_U[(2 * j + 1) * 128 + 2 * k0]     = tim;
            g_U[(2 * j + 1) * 128 + 2 * k0 + 1] = tre;
        }
    }
}

// ---------------------------------------------------------------------------
// Kernel 2: per 128-sample tile, 256 threads.
//   smem floats: U[128x132] | A[128x132] | xs[128x66] | gb[128]
// GEMM D[s][n] = sum_k A[s][k] * U[n][k] via mma.sync m16n8k8 tf32.
// Warp w computes rows [16w, 16w+16) x all 128 cols.
// ---------------------------------------------------------------------------
#define SU 132
#define SX 66
#define U_OFF 0
#define A_OFF 16896
#define X_OFF 33792
#define GB_OFF 42240
#define SMEM_FLOATS 42368
#define SMEM_BYTES (SMEM_FLOATS * 4)

#define MMA_TF32(ac, a0, a1, a2, a3, b0, b1)                                   \
    asm volatile("mma.sync.aligned.m16n8k8.row.col.f32.tf32.tf32.f32 "         \
        "{%0,%1,%2,%3}, {%4,%5,%6,%7}, {%8,%9}, {%0,%1,%2,%3};"                \
        : "+f"((ac)[0]), "+f"((ac)[1]), "+f"((ac)[2]), "+f"((ac)[3])           \
        : "r"(a0), "r"(a1), "r"(a2), "r"(a3), "r"(b0), "r"(b1))

__global__ void __launch_bounds__(256)
ffb_main(const float* __restrict__ x, const float* __restrict__ gamma,
         const float* __restrict__ beta, float* __restrict__ out) {
    extern __shared__ __align__(16) float sm[];
    float* Us = sm + U_OFF;
    float* As = sm + A_OFF;
    float* xs = sm + X_OFF;
    float* gb = sm + GB_OFF;

    const int t = threadIdx.x;

    // ---- stage gamma/beta, U, x ----
    if (t < 64) gb[t] = __ldg(gamma + t);
    else if (t < 128) gb[t] = __ldg(beta + t - 64);
    {
        const float4* gu = (const float4*)g_U;
#pragma unroll
        for (int q = 0; q < 16; ++q) {
            int idx = t + 256 * q;
            int n = idx >> 5, k = (idx & 31) * 4;
            *(float4*)(Us + n * SU + k) = gu[idx];
        }
        const float4* gx = (const float4*)(x + (size_t)blockIdx.x * 8192);
#pragma unroll
        for (int q = 0; q < 8; ++q) {
            int idx = t + 256 * q;
            int row = idx >> 4, c4 = idx & 15;
            float4 v = gx[idx];
            float* d = xs + row * SX + c4 * 4;
            *(float2*)d = f2(v.x, v.y);
            *(float2*)(d + 2) = f2(v.z, v.w);
        }
    }
    __syncthreads();

    // ---- build encoded product state for sample t (threads 0..127) ----
    if (t < 128) {
        const float* xr = xs + t * SX;
        float Ar[6], Brr[6], Bri[6];
#pragma unroll
        for (int w = 0; w < 6; ++w) {
            float r1 = xr[2 * w];
            float e1 = __expf(r1);
            float ch1 = 0.5f * (e1 + __fdividef(1.0f, e1));
            float cw = rsqrtf(ch1);
            float rd = xr[28 + 2 * w], phid = xr[29 + 2 * w];
            float pref = __expf(-0.5f * rd * rd);
            float kk = xr[40 + w];
            float r2 = xr[46 + 2 * w];
            float e2 = __expf(r2);
            float ch2 = 0.5f * (e2 + __fdividef(1.0f, e2));
            float s0 = rsqrtf(ch2);
            float s1 = s0 * __fdividef(1.0f, ch2);
            float sn, cs;
            __sincosf(phid + kk + xr[58 + w], &sn, &cs);
            float base = cw * pref;
            Ar[w] = base * s0;
            float bm = base * rd * s1;
            Brr[w] = bm * cs;
            Bri[w] = bm * sn;
        }
        float2 Rr[32], Ri[32];
        Rr[0] = f2(Ar[5], Brr[5]);
        Ri[0] = f2(0.0f, Bri[5]);
#pragma unroll
        for (int w = 4; w >= 0; --w) {
            const int PL = 1 << (4 - w);
            const float2 vA = bc(Ar[w]), vBr = bc(Brr[w]), vBi = bc(Bri[w]), vnBi = bc(-Bri[w]);
#pragma unroll
            for (int j = 0; j < 16; ++j)
                if (j < PL) {
                    float2 ar = Rr[j], ai = Ri[j];
                    Rr[PL + j] = fma2(ai, vnBi, mul2(ar, vBr));
                    Ri[PL + j] = fma2(ai, vBr, mul2(ar, vBi));
                    Rr[j] = mul2(ar, vA);
                    Ri[j] = mul2(ai, vA);
                }
        }
        // A row t, col 4p..4p+3 = (re a2p, im a2p, re a2p+1, im a2p+1), tf32
#pragma unroll
        for (int p = 0; p < 32; ++p)
            *(float4*)(As + t * SU + 4 * p) =
                make_float4(tf32r(Rr[p].x), tf32r(Ri[p].x), tf32r(Rr[p].y), tf32r(Ri[p].y));
    }
    __syncthreads();

    // ---- GEMM: warp w -> rows [16w, 16w+16) ----
    const int lane = t & 31, w = t >> 5;
    const int qr = lane >> 2, qc = lane & 3;

    float acc[16][4];
#pragma unroll
    for (int nf = 0; nf < 16; ++nf) {
        acc[nf][0] = 0.f; acc[nf][1] = 0.f; acc[nf][2] = 0.f; acc[nf][3] = 0.f;
    }

    const uint32_t* pA0 = (const uint32_t*)(As + (16 * w + qr) * SU + qc);
    const uint32_t* pA1 = pA0 + 8 * SU;
    const uint32_t* pB = (const uint32_t*)(Us + qr * SU + qc);

#pragma unroll
    for (int kk = 0; kk < 16; ++kk) {
        const int ko = 8 * kk;
        uint32_t a0 = pA0[ko], a1 = pA1[ko], a2 = pA0[ko + 4], a3 = pA1[ko + 4];
#pragma unroll
        for (int nf = 0; nf < 16; ++nf) {
            uint32_t b0 = pB[nf * (8 * SU) + ko];
            uint32_t b1 = pB[nf * (8 * SU) + ko + 4];
            MMA_TF32(acc[nf], a0, a1, a2, a3, b0, b1);
        }
    }

    // ---- epilogue: thread holds rows (r0, r1), features j = qc + 4*nf ----
    const int r0 = 16 * w + qr, r1 = r0 + 8;
    float y0[16], y1[16];
    float s0 = 0.f, s1 = 0.f;
#pragma unroll
    for (int nf = 0; nf < 16; ++nf) {
        int j = qc + 4 * nf;
        float p0 = acc[nf][0] * acc[nf][0] + acc[nf][1] * acc[nf][1];
        float p1 = acc[nf][2] * acc[nf][2] + acc[nf][3] * acc[nf][3];
        y0[nf] = p0 + xs[r0 * SX + j];
        y1[nf] = p1 + xs[r1 * SX + j];
        s0 += y0[nf];
        s1 += y1[nf];
    }
    s0 += __shfl_xor_sync(0xffffffffu, s0, 1);
    s0 += __shfl_xor_sync(0xffffffffu, s0, 2);
    s1 += __shfl_xor_sync(0xffffffffu, s1, 1);
    s1 += __shfl_xor_sync(0xffffffffu, s1, 2);
    float mean0 = s0 * 0.015625f, mean1 = s1 * 0.015625f;

    float v0 = 0.f, v1 = 0.f;
#pragma unroll
    for (int nf = 0; nf < 16; ++nf) {
        float d0 = y0[nf] - mean0, d1 = y1[nf] - mean1;
        y0[nf] = d0; y1[nf] = d1;
        v0 += d0 * d0;
        v1 += d1 * d1;
    }
    v0 += __shfl_xor_sync(0xffffffffu, v0, 1);
    v0 += __shfl_xor_sync(0xffffffffu, v0, 2);
    v1 += __shfl_xor_sync(0xffffffffu, v1, 1);
    v1 += __shfl_xor_sync(0xffffffffu, v1, 2);
    float inv0 = rsqrtf(v0 * 0.015625f + 1e-5f);
    float inv1 = rsqrtf(v1 * 0.015625f + 1e-5f);

#pragma unroll
    for (int nf = 0; nf < 16; ++nf) {
        int j = qc + 4 * nf;
        xs[r0 * SX + j] = y0[nf] * inv0 * gb[j] + gb[64 + j];
        xs[r1 * SX + j] = y1[nf] * inv1 * gb[j] + gb[64 + j];
    }
    __syncthreads();

    // ---- coalesced store ----
    {
        float4* go = (float4*)(out + (size_t)blockIdx.x * 8192);
#pragma unroll
        for (int q = 0; q < 8; ++q) {
            int idx = t + 256 * q;
            int row = idx >> 4, c4 = idx & 15;
            const float* s = xs + row * SX + c4 * 4;
            float2 a = *(const float2*)s;
            float2 b = *(const float2*)(s + 2);
            go[idx] = make_float4(a.x, a.y, b.x, b.y);
        }
    }
}

extern "C" void kernel_launch(void* const* d_in, const int* in_sizes, int n_in,
                              void* d_out, int out_size) {
    const float* x = (const float*)d_in[0];
    const float* var = (const float*)d_in[1];
    const float* gamma = (const float*)d_in[2];
    const float* beta = (const float*)d_in[3];
    float* out = (float*)d_out;

    cudaFuncSetAttribute(ffb_main, cudaFuncAttributeMaxDynamicSharedMemorySize, SMEM_BYTES);

    build_u_kernel<<<1, 64>>>(var);
    int nrows = in_sizes[0] / 64;  // 131072
    int blocks = nrows / 128;      // 1024
    ffb_main<<<blocks, 256, SMEM_BYTES>>>(x, gamma, beta, out);
}